// round 15
// baseline (speedup 1.0000x reference)
#include <cuda_runtime.h>
#include <cuda_fp16.h>
#include <math.h>
#include <stdint.h>

#define Bsz 64
#define Hd  1024
#define Ed  1024
#define Vv  32000
#define Ll  2
#define Tt  64
#define START_TOK 1

#define VT 128                        // rows per MMA tile
#define NBLK_SCORE (Vv / VT)          // 250
#define KC 64                         // fp16 K elems per chunk (128B rows)
#define NCH 16                        // score K chunks (1024/64)
#define NCH_L 4                       // lstm chunks per slice (256/64)
#define NSLICE_L 8                    // lstm K-split
#define NCH_O 8                       // o2emb chunks per slice (512/64)
#define A_PART 16384                  // 128 rows * 128B (one fp16 part)
#define B_PART 8192                   // 64 rows * 128B
#define A_REGION (2 * A_PART)         // 32768
#define B_REGION (2 * B_PART)         // 16384
#define STAGE_BYTES (A_REGION + B_REGION)  // 49152
#define DYN_BYTES (2 * STAGE_BYTES + 1024)  // 2-stage, ~99KB -> 2 CTAs/SM

typedef unsigned long long ull;

// ---------------- persistent device state ----------------
__device__ float  g_cbuf[Ll][Bsz][Hd];
__device__ int    g_xt[Bsz];
__device__ float  g_pval[Bsz][NBLK_SCORE];
__device__ int    g_pidx[Bsz][NBLK_SCORE];
__device__ float  g_gpart[NSLICE_L][Bsz][4 * Hd];
__device__ float  g_opart[2][Bsz][Ed];
__device__ int    g_cnt;

// pre-swizzled fp16x2 buffers (bulk-copy sources)
__device__ __align__(128) unsigned char g_wS[(size_t)NBLK_SCORE * NCH * A_REGION];   // score_w
__device__ __align__(128) unsigned char g_lwS[(size_t)Ll * 2 * 32 * 16 * A_REGION]; // lstm w
__device__ __align__(128) unsigned char g_o2S[(size_t)8 * NCH * A_REGION];          // o2emb w
// per-step B operands: [16 chunks][2 parts][64 rows x 128B swizzled]
__device__ __align__(128) unsigned char g_xS[NCH * B_REGION];          // emb gather
__device__ __align__(128) unsigned char g_hS[Ll][NCH * B_REGION];      // h splits
__device__ __align__(128) unsigned char g_oS[NCH * B_REGION];          // hid splits

// ---------------- helpers ----------------
__device__ __forceinline__ float sigmoidf_(float x) { return 1.0f / (1.0f + expf(-x)); }

__device__ __forceinline__ uint32_t smem_u32(const void* p) {
    uint32_t a;
    asm("{ .reg .u64 t; cvta.to.shared.u64 t, %1; cvt.u32.u64 %0, t; }" : "=r"(a) : "l"(p));
    return a;
}
__device__ __forceinline__ void ldsm_x4(uint32_t* r, uint32_t addr) {
    asm volatile("ldmatrix.sync.aligned.m8n8.x4.shared.b16 {%0,%1,%2,%3}, [%4];"
                 : "=r"(r[0]), "=r"(r[1]), "=r"(r[2]), "=r"(r[3]) : "r"(addr));
}
__device__ __forceinline__ void mma_f16(float* d, const uint32_t* a, uint32_t b0, uint32_t b1) {
    asm volatile(
        "mma.sync.aligned.m16n8k16.row.col.f32.f16.f16.f32 "
        "{%0,%1,%2,%3}, {%4,%5,%6,%7}, {%8,%9}, {%0,%1,%2,%3};"
        : "+f"(d[0]), "+f"(d[1]), "+f"(d[2]), "+f"(d[3])
        : "r"(a[0]), "r"(a[1]), "r"(a[2]), "r"(a[3]), "r"(b0), "r"(b1));
}
__device__ __forceinline__ uint32_t swz(uint32_t off) { return off ^ ((off >> 3) & 0x70); }

__device__ __forceinline__ void cpbulk(uint32_t dst, const void* src, uint32_t bytes, uint32_t mbar) {
    asm volatile("cp.async.bulk.shared::cluster.global.mbarrier::complete_tx::bytes [%0], [%1], %2, [%3];"
                 :: "r"(dst), "l"(src), "r"(bytes), "r"(mbar) : "memory");
}
__device__ __forceinline__ void mbar_init(uint32_t mb, uint32_t cnt) {
    asm volatile("mbarrier.init.shared.b64 [%0], %1;" :: "r"(mb), "r"(cnt) : "memory");
}
__device__ __forceinline__ void mbar_expect(uint32_t mb, uint32_t bytes) {
    asm volatile("mbarrier.arrive.expect_tx.shared.b64 _, [%0], %1;" :: "r"(mb), "r"(bytes) : "memory");
}
__device__ __forceinline__ void mbar_wait(uint32_t mbar, uint32_t parity) {
    asm volatile(
        "{\n\t.reg .pred P1;\n\t"
        "WAIT_LOOP_%=:\n\t"
        "mbarrier.try_wait.parity.acquire.cta.shared::cta.b64 P1, [%0], %1, 0x989680;\n\t"
        "@P1 bra.uni WAIT_DONE_%=;\n\t"
        "bra.uni WAIT_LOOP_%=;\n\t"
        "WAIT_DONE_%=:\n\t}"
        :: "r"(mbar), "r"(parity) : "memory");
}

__device__ __forceinline__ void split8(const float* s, __half* h0, __half* h1) {
#pragma unroll
    for (int i = 0; i < 8; i++) {
        float w = s[i];
        __half a = __float2half_rn(w);
        h0[i] = a;
        h1[i] = __float2half_rn(w - __half2float(a));
    }
}

// ---------------- init ----------------
__global__ void init_kernel() {
    int idx = blockIdx.x * blockDim.x + threadIdx.x;
    if (idx < Ll * Bsz * Hd) (&g_cbuf[0][0][0])[idx] = 0.0f;
    if (idx < (int)(sizeof(g_hS) / 4)) ((int*)g_hS)[idx] = 0;
    if (idx < Bsz) g_xt[idx] = START_TOK;
    if (idx == 0) g_cnt = 0;
}

// ---------------- one-time builds: pre-swizzled fp16x2 weight images ----------------
__global__ __launch_bounds__(256) void build_wS_kernel(const float* __restrict__ sw) {
    const size_t units = (size_t)Vv * Ed / 8;
    for (size_t u = blockIdx.x * 256ull + threadIdx.x; u < units; u += (size_t)gridDim.x * 256ull) {
        size_t v = u >> 7;
        int uu = (int)(u & 127);
        int ch = uu >> 3, cb = uu & 7;
        int tile = (int)(v >> 7), r = (int)(v & 127);
        __half h0[8], h1[8];
        split8(sw + v * Ed + ch * 64 + cb * 8, h0, h1);
        size_t base = ((size_t)tile * NCH + ch) * A_REGION;
        uint32_t so = swz((uint32_t)(r * 128 + cb * 16));
        *(uint4*)(g_wS + base + so)           = *(uint4*)h0;
        *(uint4*)(g_wS + base + A_PART + so)  = *(uint4*)h1;
    }
}
__global__ __launch_bounds__(256) void build_lwS_kernel(const float* __restrict__ w_ih,
                                                        const float* __restrict__ w_hh) {
    const size_t per_units = (size_t)4 * Hd * Hd / 8;
    const size_t units = per_units * Ll * 2;
    const size_t per = (size_t)4 * Hd * Hd;
    for (size_t u = blockIdx.x * 256ull + threadIdx.x; u < units; u += (size_t)gridDim.x * 256ull) {
        int mat = (int)(u / per_units);
        size_t rem = u % per_units;
        size_t row = rem >> 7;
        int uu = (int)(rem & 127);
        int ch = uu >> 3, cb = uu & 7;
        int nt = (int)(row >> 7), r = (int)(row & 127);
        int layer = mat >> 1, m = mat & 1;
        const float* src = (m ? w_hh : w_ih) + (size_t)layer * per + row * Hd + ch * 64 + cb * 8;
        __half h0[8], h1[8];
        split8(src, h0, h1);
        size_t base = ((((size_t)mat * 32 + nt) * 16 + ch)) * A_REGION;
        uint32_t so = swz((uint32_t)(r * 128 + cb * 16));
        *(uint4*)(g_lwS + base + so)          = *(uint4*)h0;
        *(uint4*)(g_lwS + base + A_PART + so) = *(uint4*)h1;
    }
}
__global__ __launch_bounds__(256) void build_o2S_kernel(const float* __restrict__ o2w) {
    const size_t units = (size_t)Ed * Hd / 8;   // 131072
    for (size_t u = blockIdx.x * 256ull + threadIdx.x; u < units; u += (size_t)gridDim.x * 256ull) {
        size_t v = u >> 7;
        int uu = (int)(u & 127);
        int ch = uu >> 3, cb = uu & 7;
        int tile = (int)(v >> 7), r = (int)(v & 127);
        __half h0[8], h1[8];
        split8(o2w + v * Hd + ch * 64 + cb * 8, h0, h1);
        size_t base = ((size_t)tile * NCH + ch) * A_REGION;
        uint32_t so = swz((uint32_t)(r * 128 + cb * 16));
        *(uint4*)(g_o2S + base + so)          = *(uint4*)h0;
        *(uint4*)(g_o2S + base + A_PART + so) = *(uint4*)h1;
    }
}

// ---------------- initial embed gather (t=0 only; later steps fused into score) --------
__global__ __launch_bounds__(256) void embed_kernel(const float* __restrict__ emb) {
    int idx = blockIdx.x * 256 + threadIdx.x;   // 8192
    int r = idx >> 7;
    int uu = idx & 127;
    int ch = uu >> 3, cb = uu & 7;
    __half h0[8], h1[8];
    split8(emb + (size_t)g_xt[r] * Ed + ch * 64 + cb * 8, h0, h1);
    size_t base = (size_t)ch * B_REGION;
    uint32_t so = swz((uint32_t)(r * 128 + cb * 16));
    *(uint4*)(g_xS + base + so)          = *(uint4*)h0;
    *(uint4*)(g_xS + base + B_PART + so) = *(uint4*)h1;
}

// ---------------- generic MMA mainloop (A tile 128 rows x K, B 64 x K) -----------------
// returns acc; caller provides chunk source bases
struct MmaCtx {
    uint32_t dbase, mbU;
    int tid, wid, lane;
};
__device__ __forceinline__ void mma_mainloop(
    const MmaCtx& cx, const unsigned char* abase, const unsigned char* bbase,
    const int* achunks, const int* bchunks, int nch, float acc[8][4])
{
    const int arow = 16 * cx.wid + (cx.lane & 15);
    const int asel = (cx.lane >> 4) & 1;
    const int brow = ((cx.lane & 16) ? 8 : 0) + (cx.lane & 7);
    const int bsel = (cx.lane >> 3) & 1;

    auto issue = [&](int c, int stg) {
        uint32_t mb = cx.mbU + 8 * stg;
        uint32_t sb = cx.dbase + stg * STAGE_BYTES;
        mbar_expect(mb, STAGE_BYTES);
        cpbulk(sb,            abase + (size_t)achunks[c] * A_REGION, A_REGION, mb);
        cpbulk(sb + A_REGION, bbase + (size_t)bchunks[c] * B_REGION, B_REGION, mb);
    };
    if (cx.tid == 0) { issue(0, 0); if (nch > 1) issue(1, 1); }

    for (int c = 0; c < nch; c++) {
        const int stg = c & 1;
        mbar_wait(cx.mbU + 8 * stg, (c >> 1) & 1);

        const uint32_t sbase = cx.dbase + stg * STAGE_BYTES;
        const uint32_t bb = sbase + A_REGION;
#pragma unroll
        for (int kk = 0; kk < 4; kk++) {
            const uint32_t aoff = swz((uint32_t)(arow * 128 + (kk * 2 + asel) * 16));
            uint32_t a0[4], a1[4];
            ldsm_x4(a0, sbase + 0 * A_PART + aoff);
            ldsm_x4(a1, sbase + 1 * A_PART + aoff);
#pragma unroll
            for (int jp = 0; jp < 4; jp++) {
                const uint32_t boff = swz((uint32_t)((jp * 16 + brow) * 128 + (kk * 2 + bsel) * 16));
                uint32_t b[4];
                ldsm_x4(b, bb + 0 * B_PART + boff);
                mma_f16(acc[2 * jp + 0], a0, b[0], b[1]);
                mma_f16(acc[2 * jp + 1], a0, b[2], b[3]);
                mma_f16(acc[2 * jp + 0], a1, b[0], b[1]);
                mma_f16(acc[2 * jp + 1], a1, b[2], b[3]);
                ldsm_x4(b, bb + 1 * B_PART + boff);
                mma_f16(acc[2 * jp + 0], a0, b[0], b[1]);
                mma_f16(acc[2 * jp + 1], a0, b[2], b[3]);
            }
        }
        __syncthreads();
        if (cx.tid == 0 && c + 2 < nch) issue(c + 2, stg);
    }
}

// ---------------- LSTM partial GEMM ----------------
__global__ __launch_bounds__(256, 2) void lstm_mma_kernel(int layer)
{
    extern __shared__ char dynsm[];
    __shared__ __align__(8) ull s_mb[2];

    const int tid  = threadIdx.x;
    const int n0   = blockIdx.x * VT;
    const int slice = blockIdx.y;
    const int m    = (slice >= 4) ? 1 : 0;

    MmaCtx cx{(smem_u32(dynsm) + 1023u) & ~1023u, smem_u32(&s_mb[0]), tid, tid >> 5, tid & 31};

    const unsigned char* abase = g_lwS + (((size_t)(layer * 2 + m) * 32 + blockIdx.x) * 16) * A_REGION;
    const unsigned char* bbase = (layer == 0)
        ? ((slice < 4) ? g_xS : g_hS[0])
        : ((slice < 4) ? g_hS[0] : g_hS[1]);

    if (tid == 0) { mbar_init(cx.mbU, 1); mbar_init(cx.mbU + 8, 1); }
    __syncthreads();

    int achunks[NCH_L], bchunks[NCH_L];
#pragma unroll
    for (int c = 0; c < NCH_L; c++) { achunks[c] = (slice & 3) * NCH_L + c; bchunks[c] = achunks[c]; }

    float acc[8][4];
#pragma unroll
    for (int j = 0; j < 8; j++)
#pragma unroll
        for (int q = 0; q < 4; q++) acc[j][q] = 0.0f;

    mma_mainloop(cx, abase, bbase, achunks, bchunks, NCH_L, acc);

    // epilogue: smem transpose -> coalesced partial writes
    float* red = (float*)dynsm + ((cx.dbase - smem_u32(dynsm)) >> 2);
    const int r1 = 16 * cx.wid + (cx.lane >> 2);
    const int r2 = r1 + 8;
#pragma unroll
    for (int j = 0; j < 8; j++) {
        int cc = j * 8 + (cx.lane & 3) * 2;
        red[r1 * 65 + cc + 0] = acc[j][0];
        red[r1 * 65 + cc + 1] = acc[j][1];
        red[r2 * 65 + cc + 0] = acc[j][2];
        red[r2 * 65 + cc + 1] = acc[j][3];
    }
    __syncthreads();
    {
        const int b  = tid >> 2;
        const int v0 = (tid & 3) * 32;
#pragma unroll 8
        for (int i = 0; i < 32; i++)
            g_gpart[slice][b][n0 + v0 + i] = red[(v0 + i) * 65 + b];
    }
}

// ---------------- LSTM cell: vectorized x4 reduce + nonlinearity + swizzled h split ----
__global__ __launch_bounds__(256) void lstm_cell_kernel(
    const float* __restrict__ b_ih_all, const float* __restrict__ b_hh_all, int layer)
{
    const int idx = blockIdx.x * 256 + threadIdx.x;   // 16384
    const int jv  = (idx & 255) * 4;                  // j base (aligned 4)
    const int row = idx >> 8;

    float4 gi = *(const float4*)&b_ih_all[layer * 4 * Hd + 0 * Hd + jv];
    float4 gf = *(const float4*)&b_ih_all[layer * 4 * Hd + 1 * Hd + jv];
    float4 gg = *(const float4*)&b_ih_all[layer * 4 * Hd + 2 * Hd + jv];
    float4 go = *(const float4*)&b_ih_all[layer * 4 * Hd + 3 * Hd + jv];
    {
        float4 t;
        t = *(const float4*)&b_hh_all[layer * 4 * Hd + 0 * Hd + jv]; gi.x += t.x; gi.y += t.y; gi.z += t.z; gi.w += t.w;
        t = *(const float4*)&b_hh_all[layer * 4 * Hd + 1 * Hd + jv]; gf.x += t.x; gf.y += t.y; gf.z += t.z; gf.w += t.w;
        t = *(const float4*)&b_hh_all[layer * 4 * Hd + 2 * Hd + jv]; gg.x += t.x; gg.y += t.y; gg.z += t.z; gg.w += t.w;
        t = *(const float4*)&b_hh_all[layer * 4 * Hd + 3 * Hd + jv]; go.x += t.x; go.y += t.y; go.z += t.z; go.w += t.w;
    }
#pragma unroll
    for (int s = 0; s < NSLICE_L; s++) {
        float4 t;
        t = *(const float4*)&g_gpart[s][row][0 * Hd + jv]; gi.x += t.x; gi.y += t.y; gi.z += t.z; gi.w += t.w;
        t = *(const float4*)&g_gpart[s][row][1 * Hd + jv]; gf.x += t.x; gf.y += t.y; gf.z += t.z; gf.w += t.w;
        t = *(const float4*)&g_gpart[s][row][2 * Hd + jv]; gg.x += t.x; gg.y += t.y; gg.z += t.z; gg.w += t.w;
        t = *(const float4*)&g_gpart[s][row][3 * Hd + jv]; go.x += t.x; go.y += t.y; go.z += t.z; go.w += t.w;
    }
    float4 cold = *(const float4*)&g_cbuf[layer][row][jv];
    float hn[4];
    float cn[4];
    {
        float gia[4] = {gi.x, gi.y, gi.z, gi.w};
        float gfa[4] = {gf.x, gf.y, gf.z, gf.w};
        float gga[4] = {gg.x, gg.y, gg.z, gg.w};
        float goa[4] = {go.x, go.y, go.z, go.w};
        float ca[4]  = {cold.x, cold.y, cold.z, cold.w};
#pragma unroll
        for (int i = 0; i < 4; i++) {
            cn[i] = sigmoidf_(gfa[i]) * ca[i] + sigmoidf_(gia[i]) * tanhf(gga[i]);
            hn[i] = sigmoidf_(goa[i]) * tanhf(cn[i]);
        }
    }
    *(float4*)&g_cbuf[layer][row][jv] = make_float4(cn[0], cn[1], cn[2], cn[3]);

    __half h0[4], h1[4];
#pragma unroll
    for (int i = 0; i < 4; i++) {
        h0[i] = __float2half_rn(hn[i]);
        h1[i] = __float2half_rn(hn[i] - __half2float(h0[i]));
    }
    int ch = jv >> 6, cb = (jv >> 3) & 7, w = jv & 7;   // w in {0,4}
    size_t off = (size_t)ch * B_REGION + swz((uint32_t)(row * 128 + cb * 16)) + w * 2;
    *(ull*)(g_hS[layer] + off)          = *(ull*)h0;
    *(ull*)(g_hS[layer] + off + B_PART) = *(ull*)h1;
}

// ---------------- o2emb via MMA: partials ----------------
__global__ __launch_bounds__(256, 2) void o2emb_mma_kernel()
{
    extern __shared__ char dynsm[];
    __shared__ __align__(8) ull s_mb[2];

    const int tid  = threadIdx.x;
    const int n0   = blockIdx.x * VT;
    const int slice = blockIdx.y;

    MmaCtx cx{(smem_u32(dynsm) + 1023u) & ~1023u, smem_u32(&s_mb[0]), tid, tid >> 5, tid & 31};

    const unsigned char* abase = g_o2S + ((size_t)blockIdx.x * NCH) * A_REGION;
    const unsigned char* bbase = g_hS[Ll - 1];

    if (tid == 0) { mbar_init(cx.mbU, 1); mbar_init(cx.mbU + 8, 1); }
    __syncthreads();

    int achunks[NCH_O], bchunks[NCH_O];
#pragma unroll
    for (int c = 0; c < NCH_O; c++) { achunks[c] = slice * NCH_O + c; bchunks[c] = achunks[c]; }

    float acc[8][4];
#pragma unroll
    for (int j = 0; j < 8; j++)
#pragma unroll
        for (int q = 0; q < 4; q++) acc[j][q] = 0.0f;

    mma_mainloop(cx, abase, bbase, achunks, bchunks, NCH_O, acc);

    float* red = (float*)dynsm + ((cx.dbase - smem_u32(dynsm)) >> 2);
    const int r1 = 16 * cx.wid + (cx.lane >> 2);
    const int r2 = r1 + 8;
#pragma unroll
    for (int j = 0; j < 8; j++) {
        int cc = j * 8 + (cx.lane & 3) * 2;
        red[r1 * 65 + cc + 0] = acc[j][0];
        red[r1 * 65 + cc + 1] = acc[j][1];
        red[r2 * 65 + cc + 0] = acc[j][2];
        red[r2 * 65 + cc + 1] = acc[j][3];
    }
    __syncthreads();
    {
        const int b  = tid >> 2;
        const int v0 = (tid & 3) * 32;
#pragma unroll 8
        for (int i = 0; i < 32; i++)
            g_opart[slice][b][n0 + v0 + i] = red[(v0 + i) * 65 + b];
    }
}

// ---------------- o2emb combine: bias + relu -> swizzled fp16x2 split ----------------
__global__ __launch_bounds__(256) void o2emb_comb_kernel(const float* __restrict__ o2b) {
    const int idx = blockIdx.x * 256 + threadIdx.x;   // 65536
    const int n   = idx & (Ed - 1);
    const int row = idx >> 10;
    float v = g_opart[0][row][n] + g_opart[1][row][n] + o2b[n];
    v = v > 0.0f ? v : 0.0f;
    __half p0 = __float2half_rn(v);
    __half p1 = __float2half_rn(v - __half2float(p0));
    int ch = n >> 6, cb = (n >> 3) & 7, w = n & 7;
    size_t off = (size_t)ch * B_REGION + swz((uint32_t)(row * 128 + cb * 16)) + w * 2;
    *(__half*)(g_oS + off)          = p0;
    *(__half*)(g_oS + off + B_PART) = p1;
}

// ---------------- score: bulk + mma + fused argmax + fused next-token embed ------------
__global__ __launch_bounds__(256, 2) void score_mma_kernel(
    const float* __restrict__ score_b, const float* __restrict__ emb,
    float* __restrict__ out, int t, int out_size)
{
    extern __shared__ char dynsm[];
    __shared__ __align__(8) ull s_mb[2];
    __shared__ bool amLast;
    __shared__ int s_tok[Bsz];

    const int tid  = threadIdx.x;
    const int wid  = tid >> 5;
    const int lane = tid & 31;
    const int n0   = blockIdx.x * VT;

    MmaCtx cx{(smem_u32(dynsm) + 1023u) & ~1023u, smem_u32(&s_mb[0]), tid, wid, lane};

    if (tid == 0) { mbar_init(cx.mbU, 1); mbar_init(cx.mbU + 8, 1); }
    __syncthreads();

    int achunks[NCH], bchunks[NCH];
#pragma unroll
    for (int c = 0; c < NCH; c++) { achunks[c] = c; bchunks[c] = c; }

    float acc[8][4];
#pragma unroll
    for (int j = 0; j < 8; j++)
#pragma unroll
        for (int q = 0; q < 4; q++) acc[j][q] = 0.0f;

    mma_mainloop(cx, g_wS + ((size_t)blockIdx.x * NCH) * A_REGION, g_oS,
                 achunks, bchunks, NCH, acc);

    // ---------------- epilogue ----------------
    float* red = (float*)dynsm + ((cx.dbase - smem_u32(dynsm)) >> 2);  // [128][65]

    const int r1 = 16 * wid + (lane >> 2);
    const int r2 = r1 + 8;
    const float bias1 = score_b[n0 + r1];
    const float bias2 = score_b[n0 + r2];
#pragma unroll
    for (int j = 0; j < 8; j++) {
        int cc = j * 8 + (lane & 3) * 2;
        red[r1 * 65 + cc + 0] = acc[j][0] + bias1;
        red[r1 * 65 + cc + 1] = acc[j][1] + bias1;
        red[r2 * 65 + cc + 0] = acc[j][2] + bias2;
        red[r2 * 65 + cc + 1] = acc[j][3] + bias2;
    }
    __syncthreads();

    {
        const int b  = tid >> 2;
        const int v0 = (tid & 3) * 32;
        const size_t obase = (size_t)b * Tt * Vv + (size_t)t * Vv + n0 + v0;
#pragma unroll 8
        for (int i = 0; i < 32; i++) out[obase + i] = red[(v0 + i) * 65 + b];
    }

    if (tid < Bsz) {
        const int b = tid;
        float bb = -3.4e38f;
        int   bi = 0x7fffffff;
#pragma unroll 8
        for (int r = 0; r < VT; r++) {
            float v2 = red[r * 65 + b];
            int   iv = n0 + r;
            if (v2 > bb || (v2 == bb && iv < bi)) { bb = v2; bi = iv; }
        }
        g_pval[b][blockIdx.x] = bb;
        g_pidx[b][blockIdx.x] = bi;
    }
    __syncthreads();

    // last-CTA: final argmax + samples output + NEXT-STEP embed gather
    if (tid == 0) {
        __threadfence();
        int old = atomicAdd(&g_cnt, 1);
        amLast = (old == NBLK_SCORE - 1);
    }
    __syncthreads();
    if (amLast) {
        __threadfence();
        if (tid < Bsz) {
            const int b = tid;
            float bv = -3.4e38f;
            int   bi = 0x7fffffff;
#pragma unroll 5
            for (int p = 0; p < NBLK_SCORE; p++) {
                float v = g_pval[b][p];
                int   i = g_pidx[b][p];
                if (v > bv || (v == bv && i < bi)) { bv = v; bi = i; }
            }
            g_xt[b] = bi;
            s_tok[b] = bi;
            long long off = (long long)Bsz * Tt * Vv + (long long)b * Tt + t;
            if (off < (long long)out_size) out[off] = (float)bi;
        }
        if (tid == 0) g_cnt = 0;
        __syncthreads();
        // embed gather for next step (valid even on last t; unused then)
        for (int u = tid; u < 8192; u += 256) {
            int r = u >> 7;
            int uu = u & 127;
            int ch = uu >> 3, cb = uu & 7;
            __half h0[8], h1[8];
            split8(emb + (size_t)s_tok[r] * Ed + ch * 64 + cb * 8, h0, h1);
            size_t base = (size_t)ch * B_REGION;
            uint32_t so = swz((uint32_t)(r * 128 + cb * 16));
            *(uint4*)(g_xS + base + so)          = *(uint4*)h0;
            *(uint4*)(g_xS + base + B_PART + so) = *(uint4*)h1;
        }
    }
}

// ---------------- launch ----------------
extern "C" void kernel_launch(void* const* d_in, const int* in_sizes, int n_in,
                              void* d_out, int out_size) {
    const float* emb   = (const float*)d_in[0];
    const float* w_ih  = (const float*)d_in[1];
    const float* w_hh  = (const float*)d_in[2];
    const float* b_ih  = (const float*)d_in[3];
    const float* b_hh  = (const float*)d_in[4];
    const float* o2w   = (const float*)d_in[5];
    const float* o2b   = (const float*)d_in[6];
    const float* sw    = (const float*)d_in[7];
    const float* sb    = (const float*)d_in[8];
    float* out = (float*)d_out;
    (void)in_sizes; (void)n_in;

    cudaFuncSetAttribute(score_mma_kernel, cudaFuncAttributeMaxDynamicSharedMemorySize, DYN_BYTES);
    cudaFuncSetAttribute(lstm_mma_kernel, cudaFuncAttributeMaxDynamicSharedMemorySize, DYN_BYTES);
    cudaFuncSetAttribute(o2emb_mma_kernel, cudaFuncAttributeMaxDynamicSharedMemorySize, DYN_BYTES);

    init_kernel<<<512, 256>>>();
    build_wS_kernel<<<2048, 256>>>(sw);
    build_lwS_kernel<<<2048, 256>>>(w_ih, w_hh);
    build_o2S_kernel<<<512, 256>>>(o2w);
    embed_kernel<<<32, 256>>>(emb);
    for (int t = 0; t < Tt; t++) {
        lstm_mma_kernel<<<dim3(32, NSLICE_L), 256, DYN_BYTES>>>(0);
        lstm_cell_kernel<<<64, 256>>>(b_ih, b_hh, 0);
        lstm_mma_kernel<<<dim3(32, NSLICE_L), 256, DYN_BYTES>>>(1);
        lstm_cell_kernel<<<64, 256>>>(b_ih, b_hh, 1);
        o2emb_mma_kernel<<<dim3(8, 2), 256, DYN_BYTES>>>();
        o2emb_comb_kernel<<<256, 256>>>(o2b);
        score_mma_kernel<<<NBLK_SCORE, 256, DYN_BYTES>>>(sb, emb, out, t, out_size);
    }
}

// round 16
// speedup vs baseline: 1.0064x; 1.0064x over previous
#include <cuda_runtime.h>
#include <cuda_fp16.h>
#include <math.h>
#include <stdint.h>

#define Bsz 64
#define Hd  1024
#define Ed  1024
#define Vv  32000
#define Ll  2
#define Tt  64
#define START_TOK 1

#define BK 32
#define XPAD 34
#define VT 128                        // rows per MMA tile
#define NBLK_SCORE (Vv / VT)          // 250
#define KC 64                         // fp16 K elems per chunk (128B rows)
#define NCH 16                        // score K chunks (1024/64)
#define NCH_L 4                       // lstm chunks per slice (256/64)
#define NSLICE_L 8                    // lstm K-split
#define A_PART 16384                  // 128 rows * 128B (one fp16 part)
#define B_PART 8192                   // 64 rows * 128B
#define A_REGION (2 * A_PART)         // 32768
#define B_REGION (2 * B_PART)         // 16384
#define STAGE_BYTES (A_REGION + B_REGION)  // 49152
#define DYN_BYTES   (2 * STAGE_BYTES + 1024)   // lstm: 2-stage, 2 CTAs/SM
#define DYN_SCORE   (4 * STAGE_BYTES + 1024)   // score: 4-stage, 1 CTA/SM

typedef unsigned long long ull;

// ---------------- persistent device state ----------------
__device__ float  g_cbuf[Ll][Bsz][Hd];
__device__ float  g_hfp[Ll][Bsz][Hd];
__device__ int    g_xt[Bsz];
__device__ float  g_pval[Bsz][NBLK_SCORE];
__device__ int    g_pidx[Bsz][NBLK_SCORE];
__device__ float  g_gpart[NSLICE_L][Bsz][4 * Hd];
__device__ float  g_opart[2][Bsz][Ed];
__device__ int    g_cnt;

// pre-swizzled fp16x2 buffers (bulk-copy sources)
__device__ __align__(128) unsigned char g_wS[(size_t)NBLK_SCORE * NCH * A_REGION];   // score_w
__device__ __align__(128) unsigned char g_lwS[(size_t)Ll * 2 * 32 * 16 * A_REGION]; // lstm w
// per-step B operands: [16 chunks][2 parts][64 rows x 128B swizzled]
__device__ __align__(128) unsigned char g_xS[NCH * B_REGION];          // emb gather
__device__ __align__(128) unsigned char g_hS[Ll][NCH * B_REGION];      // h splits
__device__ __align__(128) unsigned char g_oS[NCH * B_REGION];          // hid splits

// ---------------- helpers ----------------
__device__ __forceinline__ void ffma2(ull &acc, ull a, ull b) {
    asm("fma.rn.f32x2 %0, %1, %2, %0;" : "+l"(acc) : "l"(a), "l"(b));
}
__device__ __forceinline__ float fsum2(ull v) {
    return __uint_as_float((unsigned)v) + __uint_as_float((unsigned)(v >> 32));
}
__device__ __forceinline__ float sigmoidf_(float x) { return 1.0f / (1.0f + expf(-x)); }

__device__ __forceinline__ uint32_t smem_u32(const void* p) {
    uint32_t a;
    asm("{ .reg .u64 t; cvta.to.shared.u64 t, %1; cvt.u32.u64 %0, t; }" : "=r"(a) : "l"(p));
    return a;
}
__device__ __forceinline__ void ldsm_x4(uint32_t* r, uint32_t addr) {
    asm volatile("ldmatrix.sync.aligned.m8n8.x4.shared.b16 {%0,%1,%2,%3}, [%4];"
                 : "=r"(r[0]), "=r"(r[1]), "=r"(r[2]), "=r"(r[3]) : "r"(addr));
}
__device__ __forceinline__ void mma_f16(float* d, const uint32_t* a, uint32_t b0, uint32_t b1) {
    asm volatile(
        "mma.sync.aligned.m16n8k16.row.col.f32.f16.f16.f32 "
        "{%0,%1,%2,%3}, {%4,%5,%6,%7}, {%8,%9}, {%0,%1,%2,%3};"
        : "+f"(d[0]), "+f"(d[1]), "+f"(d[2]), "+f"(d[3])
        : "r"(a[0]), "r"(a[1]), "r"(a[2]), "r"(a[3]), "r"(b0), "r"(b1));
}
__device__ __forceinline__ uint32_t swz(uint32_t off) { return off ^ ((off >> 3) & 0x70); }

__device__ __forceinline__ void cpbulk(uint32_t dst, const void* src, uint32_t bytes, uint32_t mbar) {
    asm volatile("cp.async.bulk.shared::cluster.global.mbarrier::complete_tx::bytes [%0], [%1], %2, [%3];"
                 :: "r"(dst), "l"(src), "r"(bytes), "r"(mbar) : "memory");
}
__device__ __forceinline__ void mbar_init(uint32_t mb, uint32_t cnt) {
    asm volatile("mbarrier.init.shared.b64 [%0], %1;" :: "r"(mb), "r"(cnt) : "memory");
}
__device__ __forceinline__ void mbar_expect(uint32_t mb, uint32_t bytes) {
    asm volatile("mbarrier.arrive.expect_tx.shared.b64 _, [%0], %1;" :: "r"(mb), "r"(bytes) : "memory");
}
__device__ __forceinline__ void mbar_wait(uint32_t mbar, uint32_t parity) {
    asm volatile(
        "{\n\t.reg .pred P1;\n\t"
        "WAIT_LOOP_%=:\n\t"
        "mbarrier.try_wait.parity.acquire.cta.shared::cta.b64 P1, [%0], %1, 0x989680;\n\t"
        "@P1 bra.uni WAIT_DONE_%=;\n\t"
        "bra.uni WAIT_LOOP_%=;\n\t"
        "WAIT_DONE_%=:\n\t}"
        :: "r"(mbar), "r"(parity) : "memory");
}

__device__ __forceinline__ void split8(const float* s, __half* h0, __half* h1) {
#pragma unroll
    for (int i = 0; i < 8; i++) {
        float w = s[i];
        __half a = __float2half_rn(w);
        h0[i] = a;
        h1[i] = __float2half_rn(w - __half2float(a));
    }
}

// ---------------- init ----------------
__global__ void init_kernel() {
    int idx = blockIdx.x * blockDim.x + threadIdx.x;
    if (idx < Ll * Bsz * Hd) (&g_cbuf[0][0][0])[idx] = 0.0f;
    if (idx < (int)(sizeof(g_hS) / 4)) ((int*)g_hS)[idx] = 0;
    if (idx < Bsz) g_xt[idx] = START_TOK;
    if (idx == 0) g_cnt = 0;
}

// ---------------- one-time builds: pre-swizzled fp16x2 weight images ----------------
__global__ __launch_bounds__(256) void build_wS_kernel(const float* __restrict__ sw) {
    const size_t units = (size_t)Vv * Ed / 8;
    for (size_t u = blockIdx.x * 256ull + threadIdx.x; u < units; u += (size_t)gridDim.x * 256ull) {
        size_t v = u >> 7;
        int uu = (int)(u & 127);
        int ch = uu >> 3, cb = uu & 7;
        int tile = (int)(v >> 7), r = (int)(v & 127);
        __half h0[8], h1[8];
        split8(sw + v * Ed + ch * 64 + cb * 8, h0, h1);
        size_t base = ((size_t)tile * NCH + ch) * A_REGION;
        uint32_t so = swz((uint32_t)(r * 128 + cb * 16));
        *(uint4*)(g_wS + base + so)           = *(uint4*)h0;
        *(uint4*)(g_wS + base + A_PART + so)  = *(uint4*)h1;
    }
}
__global__ __launch_bounds__(256) void build_lwS_kernel(const float* __restrict__ w_ih,
                                                        const float* __restrict__ w_hh) {
    const size_t per_units = (size_t)4 * Hd * Hd / 8;
    const size_t units = per_units * Ll * 2;
    const size_t per = (size_t)4 * Hd * Hd;
    for (size_t u = blockIdx.x * 256ull + threadIdx.x; u < units; u += (size_t)gridDim.x * 256ull) {
        int mat = (int)(u / per_units);
        size_t rem = u % per_units;
        size_t row = rem >> 7;
        int uu = (int)(rem & 127);
        int ch = uu >> 3, cb = uu & 7;
        int nt = (int)(row >> 7), r = (int)(row & 127);
        int layer = mat >> 1, m = mat & 1;
        const float* src = (m ? w_hh : w_ih) + (size_t)layer * per + row * Hd + ch * 64 + cb * 8;
        __half h0[8], h1[8];
        split8(src, h0, h1);
        size_t base = ((((size_t)mat * 32 + nt) * 16 + ch)) * A_REGION;
        uint32_t so = swz((uint32_t)(r * 128 + cb * 16));
        *(uint4*)(g_lwS + base + so)          = *(uint4*)h0;
        *(uint4*)(g_lwS + base + A_PART + so) = *(uint4*)h1;
    }
}

// ---------------- per-step: gather emb rows for current tokens (swizzled fp16x2) -------
__global__ __launch_bounds__(256) void embed_kernel(const float* __restrict__ emb) {
    int idx = blockIdx.x * 256 + threadIdx.x;   // 8192
    int r = idx >> 7;
    int uu = idx & 127;
    int ch = uu >> 3, cb = uu & 7;
    __half h0[8], h1[8];
    split8(emb + (size_t)g_xt[r] * Ed + ch * 64 + cb * 8, h0, h1);
    size_t base = (size_t)ch * B_REGION;
    uint32_t so = swz((uint32_t)(r * 128 + cb * 16));
    *(uint4*)(g_xS + base + so)          = *(uint4*)h0;
    *(uint4*)(g_xS + base + B_PART + so) = *(uint4*)h1;
}

// ---------------- LSTM partial GEMM: 2-stage bulk + mma.sync fp16x2 ----------------
__global__ __launch_bounds__(256, 2) void lstm_mma_kernel(int layer)
{
    extern __shared__ char dynsm[];
    __shared__ __align__(8) ull s_mb[2];

    const int tid  = threadIdx.x;
    const int wid  = tid >> 5;
    const int lane = tid & 31;
    const int n0   = blockIdx.x * VT;
    const int slice = blockIdx.y;
    const int m    = (slice >= 4) ? 1 : 0;

    const uint32_t dbase = (smem_u32(dynsm) + 1023u) & ~1023u;
    const uint32_t mbU   = smem_u32(&s_mb[0]);

    const unsigned char* abase = g_lwS + (((size_t)(layer * 2 + m) * 32 + blockIdx.x) * 16) * A_REGION;
    const unsigned char* bbase = (layer == 0)
        ? ((slice < 4) ? g_xS : g_hS[0])
        : ((slice < 4) ? g_hS[0] : g_hS[1]);

    if (tid == 0) { mbar_init(mbU, 1); mbar_init(mbU + 8, 1); }
    __syncthreads();

    auto issue = [&](int kc, int stg) {
        uint32_t mb = mbU + 8 * stg;
        uint32_t sb = dbase + stg * STAGE_BYTES;
        int gch = (slice & 3) * NCH_L + kc;
        mbar_expect(mb, STAGE_BYTES);
        cpbulk(sb,            abase + (size_t)gch * A_REGION, A_REGION, mb);
        cpbulk(sb + A_REGION, bbase + (size_t)gch * B_REGION, B_REGION, mb);
    };
    if (tid == 0) { issue(0, 0); issue(1, 1); }

    float acc[8][4];
#pragma unroll
    for (int j = 0; j < 8; j++)
#pragma unroll
        for (int q = 0; q < 4; q++) acc[j][q] = 0.0f;

    const int arow = 16 * wid + (lane & 15);
    const int asel = (lane >> 4) & 1;
    const int brow = ((lane & 16) ? 8 : 0) + (lane & 7);
    const int bsel = (lane >> 3) & 1;

    for (int c = 0; c < NCH_L; c++) {
        const int stg = c & 1;
        mbar_wait(mbU + 8 * stg, (c >> 1) & 1);

        const uint32_t sbase = dbase + stg * STAGE_BYTES;
        const uint32_t bb = sbase + A_REGION;
#pragma unroll
        for (int kk = 0; kk < 4; kk++) {
            const uint32_t aoff = swz((uint32_t)(arow * 128 + (kk * 2 + asel) * 16));
            uint32_t a0[4], a1[4];
            ldsm_x4(a0, sbase + 0 * A_PART + aoff);
            ldsm_x4(a1, sbase + 1 * A_PART + aoff);
#pragma unroll
            for (int jp = 0; jp < 4; jp++) {
                const uint32_t boff = swz((uint32_t)((jp * 16 + brow) * 128 + (kk * 2 + bsel) * 16));
                uint32_t b[4];
                ldsm_x4(b, bb + 0 * B_PART + boff);       // h0: (w0,h0),(w1,h0)
                mma_f16(acc[2 * jp + 0], a0, b[0], b[1]);
                mma_f16(acc[2 * jp + 1], a0, b[2], b[3]);
                mma_f16(acc[2 * jp + 0], a1, b[0], b[1]);
                mma_f16(acc[2 * jp + 1], a1, b[2], b[3]);
                ldsm_x4(b, bb + 1 * B_PART + boff);       // h1: (w0,h1)
                mma_f16(acc[2 * jp + 0], a0, b[0], b[1]);
                mma_f16(acc[2 * jp + 1], a0, b[2], b[3]);
            }
        }
        __syncthreads();
        if (tid == 0 && c + 2 < NCH_L) issue(c + 2, stg);
    }

    // epilogue: smem transpose -> coalesced partial writes
    float* red = (float*)dynsm + ((dbase - smem_u32(dynsm)) >> 2);   // [128][65]
    const int r1 = 16 * wid + (lane >> 2);
    const int r2 = r1 + 8;
#pragma unroll
    for (int j = 0; j < 8; j++) {
        int cc = j * 8 + (lane & 3) * 2;
        red[r1 * 65 + cc + 0] = acc[j][0];
        red[r1 * 65 + cc + 1] = acc[j][1];
        red[r2 * 65 + cc + 0] = acc[j][2];
        red[r2 * 65 + cc + 1] = acc[j][3];
    }
    __syncthreads();
    {
        const int b  = tid >> 2;
        const int v0 = (tid & 3) * 32;
#pragma unroll 8
        for (int i = 0; i < 32; i++)
            g_gpart[slice][b][n0 + v0 + i] = red[(v0 + i) * 65 + b];
    }
}

// ---------------- LSTM cell: vectorized x4 reduce + nonlinearity + h split ----------
__global__ __launch_bounds__(256) void lstm_cell_kernel(
    const float* __restrict__ b_ih_all, const float* __restrict__ b_hh_all, int layer)
{
    const int idx = blockIdx.x * 256 + threadIdx.x;   // 16384
    const int jv  = (idx & 255) * 4;
    const int row = idx >> 8;

    float4 gi = *(const float4*)&b_ih_all[layer * 4 * Hd + 0 * Hd + jv];
    float4 gf = *(const float4*)&b_ih_all[layer * 4 * Hd + 1 * Hd + jv];
    float4 gg = *(const float4*)&b_ih_all[layer * 4 * Hd + 2 * Hd + jv];
    float4 go = *(const float4*)&b_ih_all[layer * 4 * Hd + 3 * Hd + jv];
    {
        float4 t;
        t = *(const float4*)&b_hh_all[layer * 4 * Hd + 0 * Hd + jv]; gi.x += t.x; gi.y += t.y; gi.z += t.z; gi.w += t.w;
        t = *(const float4*)&b_hh_all[layer * 4 * Hd + 1 * Hd + jv]; gf.x += t.x; gf.y += t.y; gf.z += t.z; gf.w += t.w;
        t = *(const float4*)&b_hh_all[layer * 4 * Hd + 2 * Hd + jv]; gg.x += t.x; gg.y += t.y; gg.z += t.z; gg.w += t.w;
        t = *(const float4*)&b_hh_all[layer * 4 * Hd + 3 * Hd + jv]; go.x += t.x; go.y += t.y; go.z += t.z; go.w += t.w;
    }
#pragma unroll
    for (int s = 0; s < NSLICE_L; s++) {
        float4 t;
        t = *(const float4*)&g_gpart[s][row][0 * Hd + jv]; gi.x += t.x; gi.y += t.y; gi.z += t.z; gi.w += t.w;
        t = *(const float4*)&g_gpart[s][row][1 * Hd + jv]; gf.x += t.x; gf.y += t.y; gf.z += t.z; gf.w += t.w;
        t = *(const float4*)&g_gpart[s][row][2 * Hd + jv]; gg.x += t.x; gg.y += t.y; gg.z += t.z; gg.w += t.w;
        t = *(const float4*)&g_gpart[s][row][3 * Hd + jv]; go.x += t.x; go.y += t.y; go.z += t.z; go.w += t.w;
    }
    float4 cold = *(const float4*)&g_cbuf[layer][row][jv];
    float gia[4] = {gi.x, gi.y, gi.z, gi.w};
    float gfa[4] = {gf.x, gf.y, gf.z, gf.w};
    float gga[4] = {gg.x, gg.y, gg.z, gg.w};
    float goa[4] = {go.x, go.y, go.z, go.w};
    float ca[4]  = {cold.x, cold.y, cold.z, cold.w};
    float cn[4], hn[4];
#pragma unroll
    for (int i = 0; i < 4; i++) {
        cn[i] = sigmoidf_(gfa[i]) * ca[i] + sigmoidf_(gia[i]) * tanhf(gga[i]);
        hn[i] = sigmoidf_(goa[i]) * tanhf(cn[i]);
    }
    *(float4*)&g_cbuf[layer][row][jv] = make_float4(cn[0], cn[1], cn[2], cn[3]);
    *(float4*)&g_hfp[layer][row][jv]  = make_float4(hn[0], hn[1], hn[2], hn[3]);

    __half h0[4], h1[4];
#pragma unroll
    for (int i = 0; i < 4; i++) {
        h0[i] = __float2half_rn(hn[i]);
        h1[i] = __float2half_rn(hn[i] - __half2float(h0[i]));
    }
    int ch = jv >> 6, cb = (jv >> 3) & 7, w = jv & 7;   // w in {0,4}
    size_t off = (size_t)ch * B_REGION + swz((uint32_t)(row * 128 + cb * 16)) + w * 2;
    *(ull*)(g_hS[layer] + off)          = *(ull*)h0;
    *(ull*)(g_hS[layer] + off + B_PART) = *(ull*)h1;
}

// ---------------- o2emb partial GEMM (scalar FFMA2, K-split x2) ----------------
__global__ __launch_bounds__(128) void o2emb_part_kernel(const float* __restrict__ o2w)
{
    __shared__ float xs[Bsz][XPAD];
    __shared__ float ws[8][XPAD];

    const int tid   = threadIdx.x;
    const int n0    = blockIdx.x * 8;
    const int slice = blockIdx.y;
    const int koff  = slice * 512;
    const int cg    = tid & 7;
    const int rg    = tid >> 3;
    const float* xsrc = &g_hfp[Ll - 1][0][0];

    ull acc[4];
#pragma unroll
    for (int i = 0; i < 4; i++) acc[i] = 0ULL;

    float4 px[4], pw;
    {
#pragma unroll
        for (int i = 0; i < 4; i++) {
            int item = tid + 128 * i;
            int r = item >> 3, c4 = item & 7;
            px[i] = *(const float4*)&xsrc[r * Hd + koff + 4 * c4];
        }
        if (tid < 64) {
            int c = tid >> 3, c4 = tid & 7;
            pw = *(const float4*)&o2w[(size_t)(n0 + c) * Hd + koff + 4 * c4];
        }
    }

    const int NCHU = 512 / BK;   // 16
    for (int chunk = 0; chunk < NCHU; chunk++) {
#pragma unroll
        for (int i = 0; i < 4; i++) {
            int item = tid + 128 * i;
            int r = item >> 3, c4 = item & 7;
            xs[r][4 * c4 + 0] = px[i].x; xs[r][4 * c4 + 1] = px[i].y;
            xs[r][4 * c4 + 2] = px[i].z; xs[r][4 * c4 + 3] = px[i].w;
        }
        if (tid < 64) {
            int c = tid >> 3, c4 = tid & 7;
            ws[c][4 * c4 + 0] = pw.x; ws[c][4 * c4 + 1] = pw.y;
            ws[c][4 * c4 + 2] = pw.z; ws[c][4 * c4 + 3] = pw.w;
        }
        __syncthreads();

        if (chunk + 1 < NCHU) {
            int k0 = koff + (chunk + 1) * BK;
#pragma unroll
            for (int i = 0; i < 4; i++) {
                int item = tid + 128 * i;
                int r = item >> 3, c4 = item & 7;
                px[i] = *(const float4*)&xsrc[r * Hd + k0 + 4 * c4];
            }
            if (tid < 64) {
                int c = tid >> 3, c4 = tid & 7;
                pw = *(const float4*)&o2w[(size_t)(n0 + c) * Hd + k0 + 4 * c4];
            }
        }

#pragma unroll
        for (int k2 = 0; k2 < BK / 2; k2++) {
            ull wv = *(const ull*)&ws[cg][2 * k2];
#pragma unroll
            for (int i = 0; i < 4; i++) {
                ull xv = *(const ull*)&xs[4 * rg + i][2 * k2];
                ffma2(acc[i], xv, wv);
            }
        }
        __syncthreads();
    }

    const int n = n0 + cg;
#pragma unroll
    for (int i = 0; i < 4; i++)
        g_opart[slice][4 * rg + i][n] = fsum2(acc[i]);
}

// ---------------- o2emb combine: bias + relu -> swizzled fp16x2 split ----------------
__global__ __launch_bounds__(256) void o2emb_comb_kernel(const float* __restrict__ o2b) {
    const int idx = blockIdx.x * 256 + threadIdx.x;   // 65536
    const int n   = idx & (Ed - 1);
    const int row = idx >> 10;
    float v = g_opart[0][row][n] + g_opart[1][row][n] + o2b[n];
    v = v > 0.0f ? v : 0.0f;
    __half p0 = __float2half_rn(v);
    __half p1 = __float2half_rn(v - __half2float(p0));
    int ch = n >> 6, cb = (n >> 3) & 7, w = n & 7;
    size_t off = (size_t)ch * B_REGION + swz((uint32_t)(row * 128 + cb * 16)) + w * 2;
    *(__half*)(g_oS + off)          = p0;
    *(__half*)(g_oS + off + B_PART) = p1;
}

// ---------------- score: 4-stage bulk + mma.sync fp16x2 + fused final argmax ----------
__global__ __launch_bounds__(256, 1) void score_mma_kernel(
    const float* __restrict__ score_b, float* __restrict__ out, int t, int out_size)
{
    extern __shared__ char dynsm[];
    __shared__ __align__(8) ull s_mb[4];
    __shared__ bool amLast;

    const int tid  = threadIdx.x;
    const int wid  = tid >> 5;
    const int lane = tid & 31;
    const int n0   = blockIdx.x * VT;

    const uint32_t dbase = (smem_u32(dynsm) + 1023u) & ~1023u;
    const uint32_t mbU   = smem_u32(&s_mb[0]);

    if (tid == 0) {
        mbar_init(mbU, 1); mbar_init(mbU + 8, 1);
        mbar_init(mbU + 16, 1); mbar_init(mbU + 24, 1);
    }
    __syncthreads();

    auto issue = [&](int kc, int stg) {
        uint32_t mb = mbU + 8 * stg;
        uint32_t sb = dbase + stg * STAGE_BYTES;
        mbar_expect(mb, STAGE_BYTES);
        cpbulk(sb,            g_wS + ((size_t)blockIdx.x * NCH + kc) * A_REGION, A_REGION, mb);
        cpbulk(sb + A_REGION, g_oS + (size_t)kc * B_REGION, B_REGION, mb);
    };
    if (tid == 0) { issue(0, 0); issue(1, 1); issue(2, 2); issue(3, 3); }

    float acc[8][4];
#pragma unroll
    for (int j = 0; j < 8; j++)
#pragma unroll
        for (int q = 0; q < 4; q++) acc[j][q] = 0.0f;

    const int arow = 16 * wid + (lane & 15);
    const int asel = (lane >> 4) & 1;
    const int brow = ((lane & 16) ? 8 : 0) + (lane & 7);
    const int bsel = (lane >> 3) & 1;

    for (int c = 0; c < NCH; c++) {
        const int stg = c & 3;
        mbar_wait(mbU + 8 * stg, (c >> 2) & 1);

        const uint32_t sbase = dbase + stg * STAGE_BYTES;
        const uint32_t bb = sbase + A_REGION;
#pragma unroll
        for (int kk = 0; kk < 4; kk++) {
            const uint32_t aoff = swz((uint32_t)(arow * 128 + (kk * 2 + asel) * 16));
            uint32_t a0[4], a1[4];
            ldsm_x4(a0, sbase + 0 * A_PART + aoff);
            ldsm_x4(a1, sbase + 1 * A_PART + aoff);
#pragma unroll
            for (int jp = 0; jp < 4; jp++) {
                const uint32_t boff = swz((uint32_t)((jp * 16 + brow) * 128 + (kk * 2 + bsel) * 16));
                uint32_t b[4];
                ldsm_x4(b, bb + 0 * B_PART + boff);
                mma_f16(acc[2 * jp + 0], a0, b[0], b[1]);
                mma_f16(acc[2 * jp + 1], a0, b[2], b[3]);
                mma_f16(acc[2 * jp + 0], a1, b[0], b[1]);
                mma_f16(acc[2 * jp + 1], a1, b[2], b[3]);
                ldsm_x4(b, bb + 1 * B_PART + boff);
                mma_f16(acc[2 * jp + 0], a0, b[0], b[1]);
                mma_f16(acc[2 * jp + 1], a0, b[2], b[3]);
            }
        }
        __syncthreads();
        if (tid == 0 && c + 4 < NCH) issue(c + 4, stg);
    }

    // ---------------- epilogue ----------------
    float* red = (float*)dynsm + ((dbase - smem_u32(dynsm)) >> 2);  // [128][65]

    const int r1 = 16 * wid + (lane >> 2);
    const int r2 = r1 + 8;
    const float bias1 = score_b[n0 + r1];
    const float bias2 = score_b[n0 + r2];
#pragma unroll
    for (int j = 0; j < 8; j++) {
        int cc = j * 8 + (lane & 3) * 2;
        red[r1 * 65 + cc + 0] = acc[j][0] + bias1;
        red[r1 * 65 + cc + 1] = acc[j][1] + bias1;
        red[r2 * 65 + cc + 0] = acc[j][2] + bias2;
        red[r2 * 65 + cc + 1] = acc[j][3] + bias2;
    }
    __syncthreads();

    {
        const int b  = tid >> 2;
        const int v0 = (tid & 3) * 32;
        const size_t obase = (size_t)b * Tt * Vv + (size_t)t * Vv + n0 + v0;
#pragma unroll 8
        for (int i = 0; i < 32; i++) out[obase + i] = red[(v0 + i) * 65 + b];
    }

    if (tid < Bsz) {
        const int b = tid;
        float bb = -3.4e38f;
        int   bi = 0x7fffffff;
#pragma unroll 8
        for (int r = 0; r < VT; r++) {
            float v2 = red[r * 65 + b];
            int   iv = n0 + r;
            if (v2 > bb || (v2 == bb && iv < bi)) { bb = v2; bi = iv; }
        }
        g_pval[b][blockIdx.x] = bb;
        g_pidx[b][blockIdx.x] = bi;
    }
    __syncthreads();

    // last-CTA final argmax + samples output
    if (tid == 0) {
        __threadfence();
        int old = atomicAdd(&g_cnt, 1);
        amLast = (old == NBLK_SCORE - 1);
    }
    __syncthreads();
    if (amLast) {
        __threadfence();
        if (tid < Bsz) {
            const int b = tid;
            float bv = -3.4e38f;
            int   bi = 0x7fffffff;
#pragma unroll 5
            for (int p = 0; p < NBLK_SCORE; p++) {
                float v = g_pval[b][p];
                int   i = g_pidx[b][p];
                if (v > bv || (v == bv && i < bi)) { bv = v; bi = i; }
            }
            g_xt[b] = bi;
            long long off = (long long)Bsz * Tt * Vv + (long long)b * Tt + t;
            if (off < (long long)out_size) out[off] = (float)bi;
        }
        if (tid == 0) g_cnt = 0;
    }
}

// ---------------- launch ----------------
extern "C" void kernel_launch(void* const* d_in, const int* in_sizes, int n_in,
                              void* d_out, int out_size) {
    const float* emb   = (const float*)d_in[0];
    const float* w_ih  = (const float*)d_in[1];
    const float* w_hh  = (const float*)d_in[2];
    const float* b_ih  = (const float*)d_in[3];
    const float* b_hh  = (const float*)d_in[4];
    const float* o2w   = (const float*)d_in[5];
    const float* o2b   = (const float*)d_in[6];
    const float* sw    = (const float*)d_in[7];
    const float* sb    = (const float*)d_in[8];
    float* out = (float*)d_out;
    (void)in_sizes; (void)n_in;

    cudaFuncSetAttribute(score_mma_kernel, cudaFuncAttributeMaxDynamicSharedMemorySize, DYN_SCORE);
    cudaFuncSetAttribute(lstm_mma_kernel, cudaFuncAttributeMaxDynamicSharedMemorySize, DYN_BYTES);

    init_kernel<<<512, 256>>>();
    build_wS_kernel<<<2048, 256>>>(sw);
    build_lwS_kernel<<<2048, 256>>>(w_ih, w_hh);
    for (int t = 0; t < Tt; t++) {
        embed_kernel<<<32, 256>>>(emb);
        lstm_mma_kernel<<<dim3(32, NSLICE_L), 256, DYN_BYTES>>>(0);
        lstm_cell_kernel<<<64, 256>>>(b_ih, b_hh, 0);
        lstm_mma_kernel<<<dim3(32, NSLICE_L), 256, DYN_BYTES>>>(1);
        lstm_cell_kernel<<<64, 256>>>(b_ih, b_hh, 1);
        o2emb_part_kernel<<<dim3(128, 2), 128>>>(o2w);
        o2emb_comb_kernel<<<256, 256>>>(o2b);
        score_mma_kernel<<<NBLK_SCORE, 256, DYN_SCORE>>>(sb, out, t, out_size);
    }
}